// round 8
// baseline (speedup 1.0000x reference)
#include <cuda_runtime.h>
#include <cuda_bf16.h>
#include <cstddef>
#include <cstdint>

// ---------------------------------------------------------------------------
// Problem: B=4, N=1024, D=1024, H=16, P=64, DFF=4096 ; rows = 4096
// ---------------------------------------------------------------------------
using bf16 = __nv_bfloat16;
constexpr size_t SZ = (size_t)4096 * 1024;
constexpr size_t M1 = (size_t)1024 * 1024;

// ----- scratch arena: 46M floats = 184 MB (hard cap: 192 MB, proven safe) ---
//  bf16 units:
//   [0,  12M) WT_QKV : 6 x (hi 1M + lo 1M)        [persistent]
//   [12M,28M) WT_W1  : 2 x (hi 4M + lo 4M)        [persistent]
//   [28M,44M) WT_W2  : 2 x (hi 4M + lo 4M)        [persistent]
//   [44M,60M) XSPL   : x1 hi,lo ; x2 hi,lo        -- dead after QKV_1
//   [44M,60M) Z2SPL  : overlays XSPL (stream s at 44M+s*8M)
//   [60M,92M) HSPL   : one stream's h hi/lo       -- overlays F_PROJ+F_ATTN
//  float units:
//   [30M,42M) F_PROJ : 3 matrices (Q,K,V of current stream, reused)
//   [42M,46M) F_ATTN : one stream's attention out (reused)
//  s1 lives in d_out (strided), overwritten in-place by MLP2 epilogue.
__device__ float g_scratch[46 * M1];

constexpr size_t WT_QKV = 0;
constexpr size_t WT_W1  = 12 * M1;
constexpr size_t WT_W2  = 28 * M1;
constexpr size_t XSPL   = 44 * M1;
constexpr size_t Z2SPL  = 44 * M1;
constexpr size_t HSPL   = 60 * M1;
constexpr size_t F_PROJ = 30 * M1;
constexpr size_t F_ATTN = 42 * M1;

// ---------------------------------------------------------------------------
// helpers
// ---------------------------------------------------------------------------
__device__ __forceinline__ uint32_t cvta_s(const void* p)
{ return (uint32_t)__cvta_generic_to_shared(p); }

__device__ __forceinline__ void cp16(uint32_t dst, const void* src)
{ asm volatile("cp.async.cg.shared.global [%0], [%1], 16;" :: "r"(dst), "l"(src)); }
__device__ __forceinline__ void cp_commit()
{ asm volatile("cp.async.commit_group;"); }
__device__ __forceinline__ void cp_wait1()
{ asm volatile("cp.async.wait_group 1;"); }

__device__ __forceinline__ void ldsm_x4(uint32_t& r0, uint32_t& r1, uint32_t& r2, uint32_t& r3, uint32_t a)
{
    asm volatile("ldmatrix.sync.aligned.m8n8.x4.shared.b16 {%0,%1,%2,%3}, [%4];"
                 : "=r"(r0), "=r"(r1), "=r"(r2), "=r"(r3) : "r"(a));
}
__device__ __forceinline__ void mma_bf16(float* c, const uint32_t* a, const uint32_t* b)
{
    asm volatile("mma.sync.aligned.m16n8k16.row.col.f32.bf16.bf16.f32 "
                 "{%0,%1,%2,%3}, {%4,%5,%6,%7}, {%8,%9}, {%0,%1,%2,%3};"
                 : "+f"(c[0]), "+f"(c[1]), "+f"(c[2]), "+f"(c[3])
                 : "r"(a[0]), "r"(a[1]), "r"(a[2]), "r"(a[3]), "r"(b[0]), "r"(b[1]));
}

// ---------------------------------------------------------------------------
// Prep 1: transpose + fp32->bf16(hi/lo) split of weights: W[K][N] -> Wt[N][K]
// ---------------------------------------------------------------------------
struct WtSet { const float* W; bf16* hi; bf16* lo; int K; int N; };
struct WtArgs { WtSet s[10]; };

__global__ void __launch_bounds__(256)
wtsplit_kernel(WtArgs args)
{
    WtSet s = args.s[blockIdx.z];
    const int n0 = blockIdx.x << 5;
    const int k0 = blockIdx.y << 5;
    if (n0 >= s.N || k0 >= s.K) return;
    __shared__ float t[32][33];
    const int tx = threadIdx.x & 31;
    const int ty = threadIdx.x >> 5;
    #pragma unroll
    for (int i = 0; i < 4; i++) {
        int kk = ty + 8 * i;
        t[kk][tx] = s.W[(size_t)(k0 + kk) * s.N + n0 + tx];
    }
    __syncthreads();
    #pragma unroll
    for (int i = 0; i < 4; i++) {
        int rr = ty + 8 * i;
        float v = t[tx][rr];               // = W[k0+tx][n0+rr]
        bf16 h = __float2bfloat16_rn(v);
        bf16 l = __float2bfloat16_rn(v - __bfloat162float(h));
        size_t o = (size_t)(n0 + rr) * s.K + k0 + tx;
        s.hi[o] = h;
        s.lo[o] = l;
    }
}

// ---------------------------------------------------------------------------
// Prep 2: elementwise fp32 -> bf16 hi/lo split (x1, x2)
// ---------------------------------------------------------------------------
__global__ void __launch_bounds__(256)
xsplit_kernel(const float* __restrict__ x, bf16* __restrict__ hi, bf16* __restrict__ lo)
{
    size_t i = ((size_t)blockIdx.x * 256 + threadIdx.x) * 4;
    float4 v = *(const float4*)&x[i];
    bf16 h0 = __float2bfloat16_rn(v.x), h1 = __float2bfloat16_rn(v.y);
    bf16 h2 = __float2bfloat16_rn(v.z), h3 = __float2bfloat16_rn(v.w);
    ((__nv_bfloat162*)&hi[i])[0] = __halves2bfloat162(h0, h1);
    ((__nv_bfloat162*)&hi[i])[1] = __halves2bfloat162(h2, h3);
    ((__nv_bfloat162*)&lo[i])[0] = __floats2bfloat162_rn(v.x - __bfloat162float(h0), v.y - __bfloat162float(h1));
    ((__nv_bfloat162*)&lo[i])[1] = __floats2bfloat162_rn(v.z - __bfloat162float(h2), v.w - __bfloat162float(h3));
}

// ---------------------------------------------------------------------------
// mma.sync bf16 GEMM, 3x split, pre-split operands, cp.async 3-stage pipeline.
//  A: [M][K] bf16 hi/lo (K-major). B: Wt [N][K] bf16 hi/lo (K-major).
//  Block 128x128, BK=32, 8 warps (2m x 4n), warp tile 64x32.
//  MODE 0: C fp32 = . + bias ; MODE 1: bf16 hi/lo = split(relu(. + bias))
//  MODE 2: C fp32 = . + bias + add   (add may alias C; read precedes write)
// ---------------------------------------------------------------------------
struct GemmSet {
    const bf16 *Ahi, *Alo, *Bhi, *Blo;
    const float *bias, *add;
    float* C; bf16 *Chi, *Clo;
};
struct GemmArgs { GemmSet s[3]; };

constexpr int BK      = 32;
constexpr int ROWB    = 80;              // 32 bf16 + 8 pad = 80 bytes per row
constexpr int VERB_SZ = 128 * ROWB;      // 10240 B per (matrix, version)
constexpr int MATB_SZ = 2 * VERB_SZ;
constexpr int STG_SZ  = 2 * MATB_SZ;     // 40960 B per stage
constexpr int NSTG    = 3;
constexpr int TCG_SMEM = NSTG * STG_SZ;  // 122880 B

template<int MODE>
__global__ void __launch_bounds__(256, 1)
tgemm_kernel(GemmArgs args, int K, int ldc, int addld)
{
    extern __shared__ char smem[];
    const uint32_t sbase = cvta_s(smem);
    GemmSet gs = args.s[blockIdx.z];

    const int tid  = threadIdx.x;
    const int lane = tid & 31;
    const int wid  = tid >> 5;
    const int wm   = (wid & 1) << 6;
    const int wn   = (wid >> 1) << 5;
    const int rowBase = blockIdx.y << 7;
    const int colBase = blockIdx.x << 7;

    const int a_r = (lane & 7) | (((lane >> 3) & 1) << 3);
    const int a_k = (lane >> 4) << 3;
    const int b_r = (lane & 7) | ((lane >> 4) << 3);
    const int b_k = ((lane >> 3) & 1) << 3;

    // cp.async mapping: 8 x 16B per thread per stage
    const bf16* src[8];
    uint32_t dstoff[8];
    #pragma unroll
    for (int i = 0; i < 8; i++) {
        int idx = tid + i * 256;
        int mat = idx >> 10;               // 0=A, 1=B
        int r   = idx & 1023;
        int ver = r >> 9;                  // 0=hi, 1=lo
        int rem = r & 511;
        int row = rem >> 2;
        int kc  = rem & 3;
        const bf16* base;
        if (mat == 0) base = (ver ? gs.Alo : gs.Ahi) + (size_t)(rowBase + row) * K;
        else          base = (ver ? gs.Blo : gs.Bhi) + (size_t)(colBase + row) * K;
        src[i]    = base + kc * 8;
        dstoff[i] = (uint32_t)(mat * MATB_SZ + ver * VERB_SZ + row * ROWB + kc * 16);
    }

    const int nk = K / BK;
    auto issue = [&](int stage, int kt) {
        const uint32_t sb = sbase + stage * STG_SZ;
        #pragma unroll
        for (int i = 0; i < 8; i++) cp16(sb + dstoff[i], src[i] + kt * BK);
    };

    float acc[4][4][4];
    #pragma unroll
    for (int mt = 0; mt < 4; mt++)
        #pragma unroll
        for (int nt = 0; nt < 4; nt++)
            acc[mt][nt][0] = acc[mt][nt][1] = acc[mt][nt][2] = acc[mt][nt][3] = 0.f;

    issue(0, 0); cp_commit();
    issue(1, 1); cp_commit();

    for (int kt = 0; kt < nk; kt++) {
        cp_wait1();
        __syncthreads();
        if (kt + 2 < nk) issue((kt + 2) % NSTG, kt + 2);
        cp_commit();

        const uint32_t sb  = sbase + (kt % NSTG) * STG_SZ;
        const uint32_t sbB = sb + MATB_SZ;
        #pragma unroll
        for (int kk = 0; kk < BK; kk += 16) {
            uint32_t aH[4][4], aL[4][4], bH[4][2], bL[4][2];
            #pragma unroll
            for (int mt = 0; mt < 4; mt++) {
                uint32_t off = (uint32_t)((wm + mt * 16 + a_r) * ROWB + (kk + a_k) * 2);
                ldsm_x4(aH[mt][0], aH[mt][1], aH[mt][2], aH[mt][3], sb + off);
                ldsm_x4(aL[mt][0], aL[mt][1], aL[mt][2], aL[mt][3], sb + VERB_SZ + off);
            }
            #pragma unroll
            for (int np = 0; np < 2; np++) {
                uint32_t off = (uint32_t)((wn + np * 16 + b_r) * ROWB + (kk + b_k) * 2);
                ldsm_x4(bH[2*np][0], bH[2*np][1], bH[2*np+1][0], bH[2*np+1][1], sbB + off);
                ldsm_x4(bL[2*np][0], bL[2*np][1], bL[2*np+1][0], bL[2*np+1][1], sbB + VERB_SZ + off);
            }
            #pragma unroll
            for (int mt = 0; mt < 4; mt++)
                #pragma unroll
                for (int nt = 0; nt < 4; nt++) {
                    mma_bf16(acc[mt][nt], aH[mt], bH[nt]);
                    mma_bf16(acc[mt][nt], aH[mt], bL[nt]);
                    mma_bf16(acc[mt][nt], aL[mt], bH[nt]);
                }
        }
    }

    // epilogue
    #pragma unroll
    for (int nt = 0; nt < 4; nt++) {
        const int col = colBase + wn + nt * 8 + ((lane & 3) << 1);
        const float2 bias2 = *(const float2*)&gs.bias[col];
        #pragma unroll
        for (int mt = 0; mt < 4; mt++) {
            const int row0 = rowBase + wm + mt * 16 + (lane >> 2);
            const int row1 = row0 + 8;
            float2 v0 = make_float2(acc[mt][nt][0] + bias2.x, acc[mt][nt][1] + bias2.y);
            float2 v1 = make_float2(acc[mt][nt][2] + bias2.x, acc[mt][nt][3] + bias2.y);
            if (MODE == 1) {
                v0.x = fmaxf(v0.x, 0.f); v0.y = fmaxf(v0.y, 0.f);
                v1.x = fmaxf(v1.x, 0.f); v1.y = fmaxf(v1.y, 0.f);
                bf16 h00 = __float2bfloat16_rn(v0.x), h01 = __float2bfloat16_rn(v0.y);
                bf16 h10 = __float2bfloat16_rn(v1.x), h11 = __float2bfloat16_rn(v1.y);
                *(__nv_bfloat162*)&gs.Chi[(size_t)row0 * ldc + col] = __halves2bfloat162(h00, h01);
                *(__nv_bfloat162*)&gs.Chi[(size_t)row1 * ldc + col] = __halves2bfloat162(h10, h11);
                *(__nv_bfloat162*)&gs.Clo[(size_t)row0 * ldc + col] =
                    __floats2bfloat162_rn(v0.x - __bfloat162float(h00), v0.y - __bfloat162float(h01));
                *(__nv_bfloat162*)&gs.Clo[(size_t)row1 * ldc + col] =
                    __floats2bfloat162_rn(v1.x - __bfloat162float(h10), v1.y - __bfloat162float(h11));
            } else {
                if (MODE == 2) {
                    float2 a0 = *(const float2*)&gs.add[(size_t)row0 * addld + col];
                    float2 a1 = *(const float2*)&gs.add[(size_t)row1 * addld + col];
                    v0.x += a0.x; v0.y += a0.y; v1.x += a1.x; v1.y += a1.y;
                }
                *(float2*)&gs.C[(size_t)row0 * ldc + col] = v0;
                *(float2*)&gs.C[(size_t)row1 * ldc + col] = v1;
            }
        }
    }
}

// ---------------------------------------------------------------------------
// Fused cross-attention, ONE stream per launch. proj = [Q(4M) K(4M) V(4M)].
// ---------------------------------------------------------------------------
constexpr int ATTN_PAD  = 68;
constexpr int ATTN_SMEM = ATTN_PAD * (128 + 64 + 64 + 128) * 4;

__global__ void __launch_bounds__(256, 1)
attn_kernel(const float* __restrict__ proj, float* __restrict__ O)
{
    extern __shared__ float sm[];
    float* Qs = sm;
    float* Kt = sm + 128 * ATTN_PAD;
    float* Vs = Kt + 64 * ATTN_PAD;
    float* Ps = Vs + 64 * ATTN_PAD;

    const int tid = threadIdx.x;
    const int tx  = tid & 15;
    const int ty  = tid >> 4;
    const int bh  = blockIdx.y;
    const int b   = bh >> 4;
    const int h   = bh & 15;
    const int i0  = blockIdx.x << 7;
    const int hc  = h << 6;

    const float* Q  = proj;
    const float* Kp = proj + 4 * M1;
    const float* Vp = proj + 8 * M1;

    const size_t qbase = (size_t)(b * 1024 + i0) * 1024 + hc;

    #pragma unroll
    for (int t = 0; t < 8; t++) {
        int idx = tid + t * 256;
        int ir = idx >> 4;
        int pc = (idx & 15) << 2;
        *(float4*)&Qs[ir * ATTN_PAD + pc] =
            *(const float4*)&Q[qbase + (size_t)ir * 1024 + pc];
    }

    float oacc[8][4];
    float lpart[8];
    #pragma unroll
    for (int r = 0; r < 8; r++) {
        lpart[r] = 0.f;
        oacc[r][0] = oacc[r][1] = oacc[r][2] = oacc[r][3] = 0.f;
    }
    __syncthreads();

    for (int j0 = 0; j0 < 1024; j0 += 64) {
        const size_t kbase = (size_t)(b * 1024 + j0) * 1024 + hc;
        #pragma unroll
        for (int t = 0; t < 4; t++) {
            int idx = tid + t * 256;
            int jr = idx >> 4;
            int pc = (idx & 15) << 2;
            float4 kv = *(const float4*)&Kp[kbase + (size_t)jr * 1024 + pc];
            Kt[(pc + 0) * ATTN_PAD + jr] = kv.x;
            Kt[(pc + 1) * ATTN_PAD + jr] = kv.y;
            Kt[(pc + 2) * ATTN_PAD + jr] = kv.z;
            Kt[(pc + 3) * ATTN_PAD + jr] = kv.w;
            *(float4*)&Vs[jr * ATTN_PAD + pc] =
                *(const float4*)&Vp[kbase + (size_t)jr * 1024 + pc];
        }
        __syncthreads();

        float sacc[8][4];
        #pragma unroll
        for (int r = 0; r < 8; r++)
            sacc[r][0] = sacc[r][1] = sacc[r][2] = sacc[r][3] = 0.f;

        #pragma unroll 8
        for (int p = 0; p < 64; p++) {
            float4 kb = *(const float4*)&Kt[p * ATTN_PAD + (tx << 2)];
            #pragma unroll
            for (int r = 0; r < 8; r++) {
                float qa = Qs[(ty * 8 + r) * ATTN_PAD + p];
                sacc[r][0] = fmaf(qa, kb.x, sacc[r][0]);
                sacc[r][1] = fmaf(qa, kb.y, sacc[r][1]);
                sacc[r][2] = fmaf(qa, kb.z, sacc[r][2]);
                sacc[r][3] = fmaf(qa, kb.w, sacc[r][3]);
            }
        }

        #pragma unroll
        for (int r = 0; r < 8; r++) {
            float4 e;
            e.x = __expf(sacc[r][0] * 0.125f);
            e.y = __expf(sacc[r][1] * 0.125f);
            e.z = __expf(sacc[r][2] * 0.125f);
            e.w = __expf(sacc[r][3] * 0.125f);
            lpart[r] += (e.x + e.y) + (e.z + e.w);
            *(float4*)&Ps[(ty * 8 + r) * ATTN_PAD + (tx << 2)] = e;
        }
        __syncthreads();

        #pragma unroll 8
        for (int j = 0; j < 64; j++) {
            float4 vb = *(const float4*)&Vs[j * ATTN_PAD + (tx << 2)];
            #pragma unroll
            for (int r = 0; r < 8; r++) {
                float pe = Ps[(ty * 8 + r) * ATTN_PAD + j];
                oacc[r][0] = fmaf(pe, vb.x, oacc[r][0]);
                oacc[r][1] = fmaf(pe, vb.y, oacc[r][1]);
                oacc[r][2] = fmaf(pe, vb.z, oacc[r][2]);
                oacc[r][3] = fmaf(pe, vb.w, oacc[r][3]);
            }
        }
        __syncthreads();
    }

    float* lbuf = Kt;
    #pragma unroll
    for (int r = 0; r < 8; r++) lbuf[(ty * 8 + r) * 16 + tx] = lpart[r];
    __syncthreads();
    float* lsum = Vs;
    if (tid < 128) {
        float t = 0.f;
        #pragma unroll
        for (int q = 0; q < 16; q++) t += lbuf[tid * 16 + q];
        lsum[tid] = 1.0f / t;
    }
    __syncthreads();
    #pragma unroll
    for (int r = 0; r < 8; r++) {
        float inv = lsum[ty * 8 + r];
        float4 v = make_float4(oacc[r][0] * inv, oacc[r][1] * inv,
                               oacc[r][2] * inv, oacc[r][3] * inv);
        *(float4*)&O[qbase + (size_t)(ty * 8 + r) * 1024 + (tx << 2)] = v;
    }
}

// ---------------------------------------------------------------------------
// Fused per-stream: s1 = LN1(x)+attn -> d_out (strided) ; z2 = LN2(s1) hi/lo
// ---------------------------------------------------------------------------
__device__ __forceinline__ float blockReduceSum(float v, float* sbuf)
{
    #pragma unroll
    for (int o = 16; o; o >>= 1) v += __shfl_xor_sync(0xffffffffu, v, o);
    __syncthreads();
    if ((threadIdx.x & 31) == 0) sbuf[threadIdx.x >> 5] = v;
    __syncthreads();
    float t = sbuf[0];
    #pragma unroll
    for (int i = 1; i < 8; i++) t += sbuf[i];
    return t;
}

__global__ void __launch_bounds__(256)
ln_fused_kernel(const float* __restrict__ x,
                const float* __restrict__ g1, const float* __restrict__ b1,
                const float* __restrict__ g2, const float* __restrict__ b2,
                const float* __restrict__ attnB,
                float* __restrict__ s1out,           // strided, ld = 2048
                bf16* __restrict__ zh, bf16* __restrict__ zl)
{
    __shared__ float sbuf[8];
    const int row = blockIdx.x;
    const int c   = threadIdx.x << 2;
    const size_t roff = (size_t)row * 1024 + c;

    float4 xv = *(const float4*)&x[roff];
    float4 av = *(const float4*)&attnB[roff];

    float sum = (xv.x + xv.y) + (xv.z + xv.w);
    float ssq = xv.x*xv.x + xv.y*xv.y + xv.z*xv.z + xv.w*xv.w;
    sum = blockReduceSum(sum, sbuf);
    ssq = blockReduceSum(ssq, sbuf);
    const float inv = 1.0f / 1024.0f;
    float mu   = sum * inv;
    float var  = ssq * inv - mu * mu;
    float rstd = rsqrtf(var + 1e-5f);

    float4 g  = *(const float4*)&g1[c];
    float4 bb = *(const float4*)&b1[c];
    float4 sv;
    sv.x = (xv.x - mu) * rstd * g.x + bb.x + av.x;
    sv.y = (xv.y - mu) * rstd * g.y + bb.y + av.y;
    sv.z = (xv.z - mu) * rstd * g.z + bb.z + av.z;
    sv.w = (xv.w - mu) * rstd * g.w + bb.w + av.w;
    *(float4*)&s1out[(size_t)row * 2048 + c] = sv;

    float sum2 = (sv.x + sv.y) + (sv.z + sv.w);
    float ssq2 = sv.x*sv.x + sv.y*sv.y + sv.z*sv.z + sv.w*sv.w;
    sum2 = blockReduceSum(sum2, sbuf);
    ssq2 = blockReduceSum(ssq2, sbuf);
    float mu2   = sum2 * inv;
    float var2  = ssq2 * inv - mu2 * mu2;
    float rstd2 = rsqrtf(var2 + 1e-5f);

    float4 g2v = *(const float4*)&g2[c];
    float4 b2v = *(const float4*)&b2[c];
    float4 zv;
    zv.x = (sv.x - mu2) * rstd2 * g2v.x + b2v.x;
    zv.y = (sv.y - mu2) * rstd2 * g2v.y + b2v.y;
    zv.z = (sv.z - mu2) * rstd2 * g2v.z + b2v.z;
    zv.w = (sv.w - mu2) * rstd2 * g2v.w + b2v.w;

    bf16 h0 = __float2bfloat16_rn(zv.x), h1 = __float2bfloat16_rn(zv.y);
    bf16 h2 = __float2bfloat16_rn(zv.z), h3 = __float2bfloat16_rn(zv.w);
    ((__nv_bfloat162*)&zh[roff])[0] = __halves2bfloat162(h0, h1);
    ((__nv_bfloat162*)&zh[roff])[1] = __halves2bfloat162(h2, h3);
    ((__nv_bfloat162*)&zl[roff])[0] = __floats2bfloat162_rn(zv.x - __bfloat162float(h0), zv.y - __bfloat162float(h1));
    ((__nv_bfloat162*)&zl[roff])[1] = __floats2bfloat162_rn(zv.z - __bfloat162float(h2), zv.w - __bfloat162float(h3));
}

// ---------------------------------------------------------------------------
// Host launcher
// Inputs: 0 x_1, 1 x_2, (2..13) wq1,bq1,wk1,bk1,wv1,bv1,wq2,bq2,wk2,bk2,wv2,bv2,
//   14..21 h1: ln1_g,ln1_b,ln2_g,ln2_b,mlp_w1,mlp_b1,mlp_w2,mlp_b2, 22..29 h2
// ---------------------------------------------------------------------------
extern "C" void kernel_launch(void* const* d_in, const int* in_sizes, int n_in,
                              void* d_out, int out_size)
{
    (void)in_sizes; (void)n_in; (void)out_size;
    const float* x1 = (const float*)d_in[0];
    const float* x2 = (const float*)d_in[1];
    float* out = (float*)d_out;

    static float* scratch = nullptr;
    static bool inited = false;
    if (!inited) {
        cudaGetSymbolAddress((void**)&scratch, g_scratch);
        cudaFuncSetAttribute(attn_kernel,     cudaFuncAttributeMaxDynamicSharedMemorySize, ATTN_SMEM);
        cudaFuncSetAttribute(tgemm_kernel<0>, cudaFuncAttributeMaxDynamicSharedMemorySize, TCG_SMEM);
        cudaFuncSetAttribute(tgemm_kernel<1>, cudaFuncAttributeMaxDynamicSharedMemorySize, TCG_SMEM);
        cudaFuncSetAttribute(tgemm_kernel<2>, cudaFuncAttributeMaxDynamicSharedMemorySize, TCG_SMEM);
        inited = true;
    }
    bf16*  sb   = (bf16*)scratch;
    float* proj = scratch + F_PROJ;
    float* attn = scratch + F_ATTN;

    // --- prep: weight transpose+split ---
    WtArgs wa{};
    for (int z = 0; z < 6; z++)
        wa.s[z] = { (const float*)d_in[2 + 2 * z], sb + WT_QKV + (size_t)z * 2 * M1,
                    sb + WT_QKV + (size_t)z * 2 * M1 + M1, 1024, 1024 };
    for (int z = 0; z < 2; z++)
        wa.s[6 + z] = { (const float*)d_in[18 + 8 * z], sb + WT_W1 + (size_t)z * 8 * M1,
                        sb + WT_W1 + (size_t)z * 8 * M1 + 4 * M1, 1024, 4096 };
    for (int z = 0; z < 2; z++)
        wa.s[8 + z] = { (const float*)d_in[20 + 8 * z], sb + WT_W2 + (size_t)z * 8 * M1,
                        sb + WT_W2 + (size_t)z * 8 * M1 + 4 * M1, 4096, 1024 };
    wtsplit_kernel<<<dim3(128, 128, 10), 256>>>(wa);

    // --- prep: x splits (x1 at XSPL, x2 at XSPL+8M) ---
    xsplit_kernel<<<4096, 256>>>(x1, sb + XSPL,          sb + XSPL + 4 * M1);
    xsplit_kernel<<<4096, 256>>>(x2, sb + XSPL + 8 * M1, sb + XSPL + 12 * M1);

    const bf16* x1h = sb + XSPL;
    const bf16* x2h = sb + XSPL + 8 * M1;

    // QKV per stream: stream0 = {q2(w3,x2), k1(w1,x1), v1(w2,x1)};
    //                 stream1 = {q1(w0,x1), k2(w4,x2), v2(w5,x2)}
    auto qkv = [&](int s) {
        const int widx[2][3] = { {3, 1, 2}, {0, 4, 5} };
        const bf16* ain[2][3] = { {x2h, x1h, x1h}, {x1h, x2h, x2h} };
        GemmArgs qa{};
        for (int z = 0; z < 3; z++) {
            int w = widx[s][z];
            qa.s[z] = { ain[s][z], ain[s][z] + 4 * M1,
                        sb + WT_QKV + (size_t)w * 2 * M1, sb + WT_QKV + (size_t)w * 2 * M1 + M1,
                        (const float*)d_in[3 + 2 * w], nullptr,
                        proj + (size_t)z * 4 * M1, nullptr, nullptr };
        }
        tgemm_kernel<0><<<dim3(8, 32, 3), 256, TCG_SMEM>>>(qa, 1024, 1024, 0);
    };
    auto ln = [&](int s) {
        ln_fused_kernel<<<4096, 256>>>(
            s ? x2 : x1,
            (const float*)d_in[14 + 8 * s], (const float*)d_in[15 + 8 * s],
            (const float*)d_in[16 + 8 * s], (const float*)d_in[17 + 8 * s],
            attn, out + s * 1024,
            sb + Z2SPL + (size_t)s * 8 * M1, sb + Z2SPL + (size_t)s * 8 * M1 + 4 * M1);
    };

    // pipeline: QKV0 -> attn0 -> QKV1 -> LN0 -> attn1 -> LN1
    qkv(0);
    attn_kernel<<<dim3(8, 64), 256, ATTN_SMEM>>>(proj, attn);
    qkv(1);
    ln(0);
    attn_kernel<<<dim3(8, 64), 256, ATTN_SMEM>>>(proj, attn);
    ln(1);

    // per-stream MLP (h buffer reused; overlays dead proj+attn)
    for (int s = 0; s < 2; s++) {
        GemmArgs m1{};
        m1.s[0] = { sb + Z2SPL + (size_t)s * 8 * M1, sb + Z2SPL + (size_t)s * 8 * M1 + 4 * M1,
                    sb + WT_W1 + (size_t)s * 8 * M1, sb + WT_W1 + (size_t)s * 8 * M1 + 4 * M1,
                    (const float*)d_in[19 + 8 * s], nullptr,
                    nullptr, sb + HSPL, sb + HSPL + 16 * M1 };
        tgemm_kernel<1><<<dim3(32, 32, 1), 256, TCG_SMEM>>>(m1, 1024, 4096, 0);

        GemmArgs m2{};
        m2.s[0] = { sb + HSPL, sb + HSPL + 16 * M1,
                    sb + WT_W2 + (size_t)s * 8 * M1, sb + WT_W2 + (size_t)s * 8 * M1 + 4 * M1,
                    (const float*)d_in[21 + 8 * s], out + s * 1024,
                    out + s * 1024, nullptr, nullptr };
        tgemm_kernel<2><<<dim3(8, 32, 1), 256, TCG_SMEM>>>(m2, 4096, 2048, 2048);
    }
}